// round 2
// baseline (speedup 1.0000x reference)
#include <cuda_runtime.h>
#include <stdint.h>

#define HH 512
#define WW 512
#define NB 2
#define NC 4
#define NMASK (NB*NC)
#define NPIX (NB*HH*WW)

// Scratch: squared 1D row distances for each (n,c) mask (pos) and complement (neg)
__device__ float g2p_buf[(size_t)NMASK*HH*WW];
__device__ float g2n_buf[(size_t)NMASK*HH*WW];
__device__ double g_acc;
__device__ int g_present[NMASK];
__device__ int g_odd_nonzero;   // 1 if any odd 32-bit word nonzero -> targets are int32
__device__ int g_is64;          // 1 if targets stored as int64

// ---------------------------------------------------------------------------
// Init + dtype probe. targets values are 0..3; if stored as little-endian
// int64, every odd 32-bit word is zero. If any odd word in the first 8192
// words is nonzero, data must be int32 (P[false negative] ~ (1/4)^4096 ~ 0).
// ---------------------------------------------------------------------------
__global__ void __launch_bounds__(128) init_kernel(const int* __restrict__ tgt_words) {
    const int tid = threadIdx.x;
    if (tid == 0) {
        g_acc = 0.0;
        g_odd_nonzero = 0;
        #pragma unroll
        for (int i = 0; i < NMASK; i++) g_present[i] = 0;
    }
    __syncthreads();
    int found = 0;
    for (int i = tid; i < 4096; i += 128)
        if (tgt_words[2 * i + 1] != 0) found = 1;
    if (__syncthreads_or(found)) {
        if (tid == 0) g_is64 = 0;
    } else {
        if (tid == 0) g_is64 = 1;
    }
}

// ---------------------------------------------------------------------------
// Kernel 1: row pass. One block per (n, r). 4 warps, one per class.
// Computes g = min(dist_to_False_left, dist_to_False_right) for mask (t==c)
// and for complement (t!=c), exactly matching the reference scan semantics
// (carry init BIG=1e6 -> integer 1000000, all values exact in fp32).
// ---------------------------------------------------------------------------
__global__ void __launch_bounds__(128) row_pass(const int* __restrict__ tgt_words) {
    __shared__ unsigned char cls[WW];
    __shared__ int dfp[NC][WW];   // forward (left) distance, pos mask
    __shared__ int dfn[NC][WW];   // forward (left) distance, neg mask

    const int blk = blockIdx.x;          // n*H + r
    const int n = blk >> 9;
    const int r = blk & (HH - 1);
    const int tid = threadIdx.x;

    const int is64 = g_is64;
    const size_t elem_base = ((size_t)n * HH + r) * WW;
    if (is64) {
        const int* row = tgt_words + 2 * elem_base;
        for (int x = tid; x < WW; x += 128) cls[x] = (unsigned char)row[2 * x];
    } else {
        const int* row = tgt_words + elem_base;
        for (int x = tid; x < WW; x += 128) cls[x] = (unsigned char)row[x];
    }
    __syncthreads();

    const int warp = tid >> 5;
    const int lane = tid & 31;
    const int c = warp;                  // class handled by this warp

    const int KBIG = 1 << 20;
    const int SINF = 1 << 26;
    const unsigned FULL = 0xffffffffu;

    // ---------------- forward (left-to-right) ----------------
    {
        unsigned char cl[16];
        int dp = KBIG, dn = KBIG;
        bool found = false;
        #pragma unroll
        for (int i = 0; i < 16; i++) {
            cl[i] = cls[lane * 16 + i];
            bool m = (cl[i] == (unsigned char)c);
            found |= m;
            dp = m ? dp + 1 : 0;
            dn = m ? 0 : dn + 1;
        }
        int sp = (dp >= KBIG) ? SINF : dp;
        int sn = (dn >= KBIG) ? SINF : dn;
        #pragma unroll
        for (int off = 1; off < 32; off <<= 1) {
            int up_p = __shfl_up_sync(FULL, sp, off);
            int up_n = __shfl_up_sync(FULL, sn, off);
            if (lane >= off) {
                sp = min(up_p + 16 * off, sp);
                sn = min(up_n + 16 * off, sn);
            }
        }
        int ep = __shfl_up_sync(FULL, sp, 1);
        int en = __shfl_up_sync(FULL, sn, 1);
        int carp = (lane == 0) ? 1000000 : min(1000000 + 16 * lane, ep);
        int carn = (lane == 0) ? 1000000 : min(1000000 + 16 * lane, en);
        #pragma unroll
        for (int i = 0; i < 16; i++) {
            bool m = (cl[i] == (unsigned char)c);
            carp = m ? carp + 1 : 0;
            carn = m ? 0 : carn + 1;
            dfp[c][lane * 16 + i] = carp;
            dfn[c][lane * 16 + i] = carn;
        }
        if (__any_sync(FULL, found) && lane == 0)
            atomicOr(&g_present[n * NC + c], 1);
    }
    __syncwarp();

    // ---------------- backward (right-to-left), combine, write g^2 ----------------
    {
        unsigned char cl[16];
        int dp = KBIG, dn = KBIG;
        #pragma unroll
        for (int i = 0; i < 16; i++) {
            cl[i] = cls[WW - 1 - lane * 16 - i];
            bool m = (cl[i] == (unsigned char)c);
            dp = m ? dp + 1 : 0;
            dn = m ? 0 : dn + 1;
        }
        int sp = (dp >= KBIG) ? SINF : dp;
        int sn = (dn >= KBIG) ? SINF : dn;
        #pragma unroll
        for (int off = 1; off < 32; off <<= 1) {
            int up_p = __shfl_up_sync(FULL, sp, off);
            int up_n = __shfl_up_sync(FULL, sn, off);
            if (lane >= off) {
                sp = min(up_p + 16 * off, sp);
                sn = min(up_n + 16 * off, sn);
            }
        }
        int ep = __shfl_up_sync(FULL, sp, 1);
        int en = __shfl_up_sync(FULL, sn, 1);
        int carp = (lane == 0) ? 1000000 : min(1000000 + 16 * lane, ep);
        int carn = (lane == 0) ? 1000000 : min(1000000 + 16 * lane, en);

        float* gp = g2p_buf + ((size_t)(n * NC + c) * HH + r) * WW;
        float* gn = g2n_buf + ((size_t)(n * NC + c) * HH + r) * WW;
        #pragma unroll
        for (int i = 0; i < 16; i++) {
            int x = WW - 1 - lane * 16 - i;
            bool m = (cl[i] == (unsigned char)c);
            carp = m ? carp + 1 : 0;
            carn = m ? 0 : carn + 1;
            int gpv = min(carp, dfp[c][x]);
            int gnv = min(carn, dfn[c][x]);
            float fp_ = (float)gpv;
            float fn_ = (float)gnv;
            gp[x] = fp_ * fp_;
            gn[x] = fn_ * fn_;
        }
    }
}

// ---------------------------------------------------------------------------
// Column min-plus with early exit: exact min_{r'} (r-r')^2 + g2[r',x]
// ---------------------------------------------------------------------------
__device__ __forceinline__ float edt_col(const float* __restrict__ col, int r) {
    float best = col[(size_t)r * WW];
    #pragma unroll 1
    for (int d = 1;; ++d) {
        float dd = (float)(d * d);
        if (dd >= best) break;
        int a = r - d;
        int b = r + d;
        bool any = false;
        if (a >= 0)  { best = fminf(best, col[(size_t)a * WW] + dd); any = true; }
        if (b < HH)  { best = fminf(best, col[(size_t)b * WW] + dd); any = true; }
        if (!any) break;
    }
    return best;
}

// ---------------------------------------------------------------------------
// Kernel 2: fused softmax + signed EDT + reduction. One thread per pixel.
// ---------------------------------------------------------------------------
__global__ void __launch_bounds__(256) loss_pass(const float* __restrict__ logits) {
    const int idx = blockIdx.x * blockDim.x + threadIdx.x;
    double local = 0.0;
    if (idx < NPIX) {
        const int x = idx & (WW - 1);
        const int r = (idx >> 9) & (HH - 1);
        const int n = idx >> 18;
        const size_t pix = (size_t)r * WW + x;

        float l[NC];
        #pragma unroll
        for (int c = 0; c < NC; c++)
            l[c] = logits[(size_t)(n * NC + c) * HH * WW + pix];
        float mx = fmaxf(fmaxf(l[0], l[1]), fmaxf(l[2], l[3]));
        float e[NC], s = 0.0f;
        #pragma unroll
        for (int c = 0; c < NC; c++) { e[c] = expf(l[c] - mx); s += e[c]; }
        float inv_s = 1.0f / s;

        float acc = 0.0f;
        #pragma unroll 1
        for (int c = 1; c < NC; c++) {           // class 0 masked out by reference
            if (!g_present[n * NC + c]) continue;
            const size_t base = (size_t)(n * NC + c) * HH * WW + x;
            float d2p = edt_col(g2p_buf + base, r);
            float d2n = edt_col(g2n_buf + base, r);
            acc += (e[c] * inv_s) * (sqrtf(d2n) - sqrtf(d2p));
        }
        local = (double)acc;
    }

    // block reduction (double)
    __shared__ double warp_sums[8];
    const unsigned FULL = 0xffffffffu;
    #pragma unroll
    for (int off = 16; off > 0; off >>= 1)
        local += __shfl_down_sync(FULL, local, off);
    const int lane = threadIdx.x & 31;
    const int wid = threadIdx.x >> 5;
    if (lane == 0) warp_sums[wid] = local;
    __syncthreads();
    if (wid == 0) {
        double v = (lane < 8) ? warp_sums[lane] : 0.0;
        #pragma unroll
        for (int off = 4; off > 0; off >>= 1)
            v += __shfl_down_sync(FULL, v, off);
        if (lane == 0) atomicAdd(&g_acc, v);
    }
}

__global__ void finalize_kernel(float* out) {
    // mean over N*C*H*W = 2*4*512*512 = 2^21 elements (exact power of two)
    out[0] = (float)(g_acc * (1.0 / 2097152.0));
}

extern "C" void kernel_launch(void* const* d_in, const int* in_sizes, int n_in,
                              void* d_out, int out_size) {
    const float* logits = (const float*)d_in[0];     // [2,4,512,512] fp32
    const int* tgt_words = (const int*)d_in[1];      // [2,512,512] int32 or int64
    float* out = (float*)d_out;

    init_kernel<<<1, 128>>>(tgt_words);
    row_pass<<<NB * HH, 128>>>(tgt_words);
    loss_pass<<<(NPIX + 255) / 256, 256>>>(logits);
    finalize_kernel<<<1, 1>>>(out);
}